// round 1
// baseline (speedup 1.0000x reference)
#include <cuda_runtime.h>
#include <math.h>

#define B 8
#define NS 25
#define NQ 75
#define WAY 5
#define C 512
#define HW 36
#define MID 6
#define NCLS 64
#define BJ (B*NQ)      // 600
#define BI (B*WAY)     // 40
#define LOGITS_N (BJ*NCLS*HW)   // 1382400

// ---------------- scratch (device globals; no allocation) ----------------
__device__ float g_protosT[BI*HW*C];   // [b*5+i][x][c]  raw prototypes, c contiguous
__device__ float g_inv1[BI*HW];        // 1/||protos[b,i,:,x]||
__device__ float g_f1nbar[BI*C];       // mean_x f1n
__device__ float g_inv2[BJ*HW];        // 1/||query[b,j,:,y]||
__device__ float g_f2nbar[BJ*C];       // mean_y f2n
__device__ float g_h1[BI*NQ*MID];      // conv1 output path1: ((b*5+i)*75+j)*6+ch
__device__ float g_h2[BI*NQ*MID];      // conv1 output path2
__device__ float g_bnscale[2*MID];
__device__ float g_bnshift[2*MID];
__device__ float g_attsel[BJ*HW];      // sum_w qt[b,j,w]*att2[b,w,j,y]

// ---------------- K1: prototypes (class-averaged supports), transposed ----------------
__global__ void k1_protos(const float* __restrict__ sup, const float* __restrict__ st) {
    int b = blockIdx.y;
    int idx = blockIdx.x * 256 + threadIdx.x;          // < 18432 = C*HW
    __shared__ float st_s[NS*WAY];
    if (threadIdx.x < NS*WAY) st_s[threadIdx.x] = st[b*NS*WAY + threadIdx.x];
    __syncthreads();
    int c = idx / HW, x = idx % HW;
    float acc[WAY]; float cnt[WAY];
#pragma unroll
    for (int i = 0; i < WAY; i++) { acc[i] = 0.f; cnt[i] = 0.f; }
    const float* sb = sup + (size_t)b*NS*C*HW + (size_t)c*HW + x;
    for (int n = 0; n < NS; n++) {
        float v = sb[(size_t)n*C*HW];
#pragma unroll
        for (int i = 0; i < WAY; i++) { float w = st_s[n*WAY+i]; acc[i] += w*v; cnt[i] += w; }
    }
#pragma unroll
    for (int i = 0; i < WAY; i++)
        g_protosT[((size_t)(b*WAY+i)*HW + x)*C + c] = acc[i] / cnt[i];
}

// ---------------- K1b: inv1 (L2 norms over c) + f1nbar ----------------
__global__ void k1b_norms(void) {
    int bi = blockIdx.x;                                // 0..39
    __shared__ float inv1_s[HW];
    int t = threadIdx.x;                                // 512
    int w = t >> 5, lane = t & 31;
    const float* p = g_protosT + (size_t)bi*HW*C;
    for (int x = w; x < HW; x += 16) {
        float s0 = 0.f, s1 = 0.f;
        for (int c = lane; c < C; c += 64) {
            float v0 = p[x*C + c];      s0 += v0*v0;
            float v1 = p[x*C + c + 32]; s1 += v1*v1;
        }
        float s = s0 + s1;
#pragma unroll
        for (int o = 16; o; o >>= 1) s += __shfl_down_sync(0xffffffffu, s, o);
        if (lane == 0) {
            float inv = 1.f / fmaxf(sqrtf(s), 1e-12f);
            inv1_s[x] = inv;
            g_inv1[bi*HW + x] = inv;
        }
    }
    __syncthreads();
    int c = t;
    float acc = 0.f;
#pragma unroll 4
    for (int x = 0; x < HW; x++) acc += p[x*C + c] * inv1_s[x];
    g_f1nbar[bi*C + c] = acc * (1.f/HW);
}

// ---------------- K2: inv2 + f2nbar ----------------
__global__ void k2_qnorms(const float* __restrict__ query) {
    int bj = blockIdx.x;
    const float* q = query + (size_t)bj*C*HW;
    int t = threadIdx.x;                                // 288
    int y = t % HW, g = t / HW;                         // g < 8
    __shared__ float red[8*HW];
    __shared__ float inv2_s[HW];
    float ss = 0.f;
    for (int c = g; c < C; c += 8) { float v = q[c*HW + y]; ss += v*v; }
    red[g*HW + y] = ss;
    __syncthreads();
    if (t < HW) {
        float s = 0.f;
#pragma unroll
        for (int gg = 0; gg < 8; gg++) s += red[gg*HW + t];
        float inv = 1.f / fmaxf(sqrtf(s), 1e-12f);
        inv2_s[t] = inv;
        g_inv2[bj*HW + t] = inv;
    }
    __syncthreads();
    for (int c = t; c < C; c += 288) {
        float acc = 0.f;
#pragma unroll 4
        for (int yy = 0; yy < HW; yy++) acc += q[c*HW + yy] * inv2_s[yy];
        g_f2nbar[bj*C + c] = acc * (1.f/HW);
    }
}

// ---------------- K3: m1, m2 -> conv1 outputs h1, h2 ----------------
__global__ void k3_conv1(const float* __restrict__ query,
                         const float* __restrict__ w1, const float* __restrict__ b1) {
    int bj = blockIdx.x; int b = bj / NQ, j = bj % NQ;
    int t = threadIdx.x;                                // 256
    __shared__ float f1nbar_s[WAY*C];
    __shared__ float f2nbar_s[C];
    __shared__ float inv1_s[WAY*HW];
    __shared__ float inv2_s[HW];
    __shared__ float m_s[WAY*HW];
    __shared__ float w1_s[MID*HW];
    __shared__ float b1_s[MID];
    for (int k = t; k < WAY*C; k += 256) f1nbar_s[k] = g_f1nbar[b*WAY*C + k];
    for (int k = t; k < C;     k += 256) f2nbar_s[k] = g_f2nbar[bj*C + k];
    if (t < WAY*HW) inv1_s[t] = g_inv1[b*WAY*HW + t];
    if (t < HW)     inv2_s[t] = g_inv2[bj*HW + t];
    if (t < MID*HW) w1_s[t]   = w1[t];
    if (t < MID)    b1_s[t]   = b1[t];
    __syncthreads();
    const float* q = query + (size_t)bj*C*HW;
    // m1[i][y] = inv2[y] * sum_c f1nbar[i,c]*q[c,y]
    if (t < WAY*HW) {
        int i = t / HW, y = t % HW;
        float a0=0.f, a1=0.f, a2=0.f, a3=0.f;
        const float* fb = f1nbar_s + i*C;
        for (int c = 0; c < C; c += 4) {
            a0 += fb[c+0] * q[(c+0)*HW + y];
            a1 += fb[c+1] * q[(c+1)*HW + y];
            a2 += fb[c+2] * q[(c+2)*HW + y];
            a3 += fb[c+3] * q[(c+3)*HW + y];
        }
        m_s[t] = ((a0+a1)+(a2+a3)) * inv2_s[y];
    }
    __syncthreads();
    if (t < WAY*MID) {
        int i = t / MID, ch = t % MID;
        float h = b1_s[ch];
#pragma unroll 4
        for (int y = 0; y < HW; y++) h += w1_s[ch*HW + y] * m_s[i*HW + y];
        g_h1[((b*WAY+i)*NQ + j)*MID + ch] = h;
    }
    __syncthreads();
    // m2[i][x] = inv1[i,x] * sum_c protosT[i,x,c]*f2nbar[c]   (warp per row)
    int w = t >> 5, lane = t & 31;
    for (int r = w; r < WAY*HW; r += 8) {
        int i = r / HW, x = r % HW;
        const float* p = g_protosT + ((size_t)(b*WAY+i)*HW + x)*C;
        float s0 = 0.f, s1 = 0.f;
        for (int c = lane; c < C; c += 64) {
            s0 += p[c]      * f2nbar_s[c];
            s1 += p[c + 32] * f2nbar_s[c + 32];
        }
        float s = s0 + s1;
#pragma unroll
        for (int o = 16; o; o >>= 1) s += __shfl_down_sync(0xffffffffu, s, o);
        if (lane == 0) m_s[r] = s * inv1_s[r];
    }
    __syncthreads();
    if (t < WAY*MID) {
        int i = t / MID, ch = t % MID;
        float h = b1_s[ch];
#pragma unroll 4
        for (int x = 0; x < HW; x++) h += w1_s[ch*HW + x] * m_s[i*HW + x];
        g_h2[((b*WAY+i)*NQ + j)*MID + ch] = h;
    }
}

// ---------------- K4: deterministic BN stats (double tree reduce) ----------------
__global__ void k4_bn(const float* __restrict__ gamma, const float* __restrict__ beta) {
    int p = blockIdx.x / MID, ch = blockIdx.x % MID;
    const float* h = p ? g_h2 : g_h1;
    int t = threadIdx.x;                                // 256
    double s = 0.0, sq = 0.0;
    for (int n = t; n < BI*NQ/WAY*WAY; n += 256) {      // n in [0,3000)
        double v = (double)h[n*MID + ch];
        s += v; sq += v*v;
    }
    __shared__ double rs[256], rq[256];
    rs[t] = s; rq[t] = sq;
    __syncthreads();
    for (int o = 128; o; o >>= 1) {
        if (t < o) { rs[t] += rs[t+o]; rq[t] += rq[t+o]; }
        __syncthreads();
    }
    if (t == 0) {
        double mu  = rs[0] / 3000.0;
        double var = rq[0] / 3000.0 - mu*mu;
        float sd = sqrtf((float)var + 1e-5f);
        float sc = gamma[ch] / sd;
        g_bnscale[p*MID + ch] = sc;
        g_bnshift[p*MID + ch] = beta[ch] - (float)mu * sc;
    }
}

// ---------------- K5: per-(b,j) attention + softmax + pooling + cls + attsel ----------------
#define QPAD 37
__global__ void k5_attn(const float* __restrict__ query,
                        const float* __restrict__ qt,
                        const float* __restrict__ w2, const float* __restrict__ b2,
                        float* __restrict__ out_cls) {
    extern __shared__ float sm[];
    float* qs     = sm;                  // [512][37]
    float* buf    = qs + C*QPAD;         // [5][512]  reused: v1 -> pp -> u
    float* attp1  = buf + WAY*C;         // 180
    float* attp2  = attp1 + WAY*HW;      // 180
    float* att_s  = attp2 + WAY*HW;      // 180
    float* s_s    = att_s + WAY*HW;      // 180
    float* inv1_s = s_s + WAY*HW;        // 180
    float* inv2_s = inv1_s + WAY*HW;     // 36
    float* w2_s   = inv2_s + HW;         // 216
    float* b2_s   = w2_s + MID*HW;       // 36
    float* scl    = b2_s + HW;           // 12
    float* shf    = scl + 2*MID;         // 12
    float* pninv  = shf + 2*MID;         // 8
    float* wred   = pninv + 8;           // 40
    float* qt_s   = wred + 40;           // 8

    int bj = blockIdx.x; int b = bj / NQ, j = bj % NQ;
    int t = threadIdx.x;                                // 256
    const float* q = query + (size_t)bj*C*HW;

    if (t < 2*MID) { scl[t] = g_bnscale[t]; shf[t] = g_bnshift[t]; }
    if (t < MID*HW) w2_s[t] = w2[t];
    if (t < HW) { b2_s[t] = b2[t]; inv2_s[t] = g_inv2[bj*HW + t]; }
    if (t < WAY*HW) inv1_s[t] = g_inv1[b*WAY*HW + t];
    if (t < WAY) qt_s[t] = qt[(b*NQ + j)*WAY + t];
    for (int k = t; k < C*HW; k += 256) { int c = k/HW, y = k%HW; qs[c*QPAD + y] = q[k]; }
    __syncthreads();

    // attention pre-activations: BN + relu + conv2 (both paths)
    if (t < WAY*HW) {
        int i = t / HW, y = t % HW;
        const float* h1p = g_h1 + ((b*WAY+i)*NQ + j)*MID;
        const float* h2p = g_h2 + ((b*WAY+i)*NQ + j)*MID;
        float a1 = b2_s[y], a2 = b2_s[y];
#pragma unroll
        for (int ch = 0; ch < MID; ch++) {
            float r1 = fmaxf(h1p[ch]*scl[ch]      + shf[ch],      0.f);
            float r2 = fmaxf(h2p[ch]*scl[MID+ch]  + shf[MID+ch],  0.f);
            a1 += w2_s[y*MID + ch] * r1;
            a2 += w2_s[y*MID + ch] * r2;
        }
        attp1[t] = a1; attp2[t] = a2;
    }
    __syncthreads();

    // v1[i][c] = (1/36) sum_y f2n[c,y] * attp1[i,y]
    for (int c = t; c < C; c += 256) {
        float a0=0.f,a1=0.f,a2=0.f,a3=0.f,a4=0.f;
#pragma unroll 4
        for (int y = 0; y < HW; y++) {
            float qv = qs[c*QPAD + y] * inv2_s[y];
            a0 += qv * attp1[0*HW + y];
            a1 += qv * attp1[1*HW + y];
            a2 += qv * attp1[2*HW + y];
            a3 += qv * attp1[3*HW + y];
            a4 += qv * attp1[4*HW + y];
        }
        buf[0*C+c]=a0*(1.f/HW); buf[1*C+c]=a1*(1.f/HW); buf[2*C+c]=a2*(1.f/HW);
        buf[3*C+c]=a3*(1.f/HW); buf[4*C+c]=a4*(1.f/HW);
    }
    __syncthreads();

    // s1[i][x] = inv1 * f1n_row . v1   (warp per row)
    int w = t >> 5, lane = t & 31;
    for (int r = w; r < WAY*HW; r += 8) {
        int i = r / HW, x = r % HW;
        const float* p = g_protosT + ((size_t)(b*WAY+i)*HW + x)*C;
        const float* v = buf + i*C;
        float s0 = 0.f, s1 = 0.f;
        for (int c = lane; c < C; c += 64) { s0 += p[c]*v[c]; s1 += p[c+32]*v[c+32]; }
        float s = s0 + s1;
#pragma unroll
        for (int o = 16; o; o >>= 1) s += __shfl_down_sync(0xffffffffu, s, o);
        if (lane == 0) s_s[r] = s * inv1_s[r];
    }
    __syncthreads();

    // softmax over x, +1  -> att1 in att_s
    if (t < WAY) {
        float mx = -1e30f;
        for (int x = 0; x < HW; x++) mx = fmaxf(mx, s_s[t*HW + x]);
        float sum = 0.f;
        for (int x = 0; x < HW; x++) sum += expf((s_s[t*HW + x] - mx) * 40.f);
        float inv = 1.f / sum;
        for (int x = 0; x < HW; x++)
            att_s[t*HW + x] = expf((s_s[t*HW + x] - mx) * 40.f) * inv + 1.f;
    }
    __syncthreads();

    // pp[i][c] = (1/36) sum_x protosT[i,x,c] * att1[i,x]
    for (int c = t; c < C; c += 256) {
        float a[WAY];
#pragma unroll
        for (int i = 0; i < WAY; i++) {
            const float* p = g_protosT + ((size_t)(b*WAY+i)*HW)*C + c;
            float ai = 0.f;
#pragma unroll 4
            for (int x = 0; x < HW; x++) ai += p[(size_t)x*C] * att_s[i*HW + x];
            a[i] = ai;
        }
#pragma unroll
        for (int i = 0; i < WAY; i++) buf[i*C + c] = a[i] * (1.f/HW);
    }
    __syncthreads();

    // proto_norm inverse: 1/max(||pp[i,:]||, eps)
    {
        float part[WAY] = {0.f,0.f,0.f,0.f,0.f};
        for (int c = t; c < C; c += 256)
#pragma unroll
            for (int i = 0; i < WAY; i++) { float v = buf[i*C + c]; part[i] += v*v; }
#pragma unroll
        for (int i = 0; i < WAY; i++) {
            float s = part[i];
#pragma unroll
            for (int o = 16; o; o >>= 1) s += __shfl_down_sync(0xffffffffu, s, o);
            if (lane == 0) wred[i*8 + w] = s;
        }
        __syncthreads();
        if (t < WAY) {
            float s = 0.f;
#pragma unroll
            for (int gg = 0; gg < 8; gg++) s += wred[t*8 + gg];
            pninv[t] = 1.f / fmaxf(sqrtf(s), 1e-12f);
        }
        __syncthreads();
    }

    // cls_scores[i][y] = 7 * inv2[y]*pninv[i] * sum_c qs[c,y]*pp[i,c]
    if (t < WAY*HW) {
        int i = t / HW, y = t % HW;
        const float* pv = buf + i*C;
        float a0=0.f,a1=0.f,a2=0.f,a3=0.f;
        for (int c = 0; c < C; c += 4) {
            a0 += qs[(c+0)*QPAD + y] * pv[c+0];
            a1 += qs[(c+1)*QPAD + y] * pv[c+1];
            a2 += qs[(c+2)*QPAD + y] * pv[c+2];
            a3 += qs[(c+3)*QPAD + y] * pv[c+3];
        }
        out_cls[((b*NQ + j)*WAY + i)*HW + y] =
            7.f * ((a0+a1)+(a2+a3)) * inv2_s[y] * pninv[i];
    }
    __syncthreads();

    // coef[i][x] = inv1*attp2/36 (into s_s), then u[i][c]
    if (t < WAY*HW) s_s[t] = inv1_s[t] * attp2[t] * (1.f/HW);
    __syncthreads();
    for (int c = t; c < C; c += 256) {
        float a[WAY];
#pragma unroll
        for (int i = 0; i < WAY; i++) {
            const float* p = g_protosT + ((size_t)(b*WAY+i)*HW)*C + c;
            float ai = 0.f;
#pragma unroll 4
            for (int x = 0; x < HW; x++) ai += p[(size_t)x*C] * s_s[i*HW + x];
            a[i] = ai;
        }
#pragma unroll
        for (int i = 0; i < WAY; i++) buf[i*C + c] = a[i];
    }
    __syncthreads();

    // s2[i][y] -> attp1
    if (t < WAY*HW) {
        int i = t / HW, y = t % HW;
        const float* uv = buf + i*C;
        float a0=0.f,a1=0.f,a2=0.f,a3=0.f;
        for (int c = 0; c < C; c += 4) {
            a0 += qs[(c+0)*QPAD + y] * uv[c+0];
            a1 += qs[(c+1)*QPAD + y] * uv[c+1];
            a2 += qs[(c+2)*QPAD + y] * uv[c+2];
            a3 += qs[(c+3)*QPAD + y] * uv[c+3];
        }
        attp1[t] = ((a0+a1)+(a2+a3)) * inv2_s[y];
    }
    __syncthreads();

    // softmax over y, +1 -> att2 in att_s
    if (t < WAY) {
        float mx = -1e30f;
        for (int y = 0; y < HW; y++) mx = fmaxf(mx, attp1[t*HW + y]);
        float sum = 0.f;
        for (int y = 0; y < HW; y++) sum += expf((attp1[t*HW + y] - mx) * 40.f);
        float inv = 1.f / sum;
        for (int y = 0; y < HW; y++)
            att_s[t*HW + y] = expf((attp1[t*HW + y] - mx) * 40.f) * inv + 1.f;
    }
    __syncthreads();

    // attsel[y] = sum_w qt[w]*att2[w,y]
    if (t < HW) {
        float a = 0.f;
#pragma unroll
        for (int wc = 0; wc < WAY; wc++) a += qt_s[wc] * att_s[wc*HW + t];
        g_attsel[bj*HW + t] = a;
    }
}
#define K5_SMEM ((C*QPAD + WAY*C + 5*WAY*HW + HW + MID*HW + HW + 2*MID + 2*MID + 8 + 40 + 8)*4)

// ---------------- K6: logits = attsel[y] * (cls_w @ f2r) + cls_b ----------------
__global__ void k6_logits(const float* __restrict__ query, const float* __restrict__ clsw,
                          const float* __restrict__ clsb, float* __restrict__ out_logits) {
    __shared__ float qs[64*40];
    __shared__ float ws[64*65];
    __shared__ float asel[HW];
    __shared__ float cb[NCLS];
    int bj = blockIdx.x;
    int t = threadIdx.x;                                // 144
    if (t < HW)   asel[t] = g_attsel[bj*HW + t];
    if (t < NCLS) cb[t]   = clsb[t];
    int og = t & 15, yg = t >> 4;                       // 16 x 9
    int o0 = og*4, y0 = yg*4;
    float acc[16];
#pragma unroll
    for (int k = 0; k < 16; k++) acc[k] = 0.f;
    const float* q = query + (size_t)bj*C*HW;
    for (int c0 = 0; c0 < C; c0 += 64) {
        __syncthreads();
        for (int k = t; k < 64*HW; k += 144) {
            int c = k / HW, y = k % HW;
            qs[c*40 + y] = q[(c0 + c)*HW + y];
        }
        for (int k = t; k < 64*64; k += 144) {
            int c = k & 63, o = k >> 6;
            ws[c*65 + o] = clsw[o*C + c0 + c];
        }
        __syncthreads();
#pragma unroll 4
        for (int cc = 0; cc < 64; cc++) {
            float w0 = ws[cc*65 + o0+0], w1v = ws[cc*65 + o0+1];
            float w2v = ws[cc*65 + o0+2], w3v = ws[cc*65 + o0+3];
            float q0 = qs[cc*40 + y0+0], q1v = qs[cc*40 + y0+1];
            float q2v = qs[cc*40 + y0+2], q3v = qs[cc*40 + y0+3];
            acc[0] += w0*q0;  acc[1] += w0*q1v;  acc[2] += w0*q2v;  acc[3] += w0*q3v;
            acc[4] += w1v*q0; acc[5] += w1v*q1v; acc[6] += w1v*q2v; acc[7] += w1v*q3v;
            acc[8] += w2v*q0; acc[9] += w2v*q1v; acc[10]+= w2v*q2v; acc[11]+= w2v*q3v;
            acc[12]+= w3v*q0; acc[13]+= w3v*q1v; acc[14]+= w3v*q2v; acc[15]+= w3v*q3v;
        }
    }
    float* op = out_logits + (size_t)bj*NCLS*HW;
#pragma unroll
    for (int oo = 0; oo < 4; oo++)
#pragma unroll
        for (int yy = 0; yy < 4; yy++)
            op[(o0+oo)*HW + y0 + yy] = asel[y0+yy]*acc[oo*4+yy] + cb[o0+oo];
}

// ---------------- launch ----------------
extern "C" void kernel_launch(void* const* d_in, const int* in_sizes, int n_in,
                              void* d_out, int out_size) {
    const float* sup   = (const float*)d_in[0];
    const float* query = (const float*)d_in[1];
    const float* st    = (const float*)d_in[2];
    const float* qt    = (const float*)d_in[3];
    const float* w1    = (const float*)d_in[4];
    const float* b1    = (const float*)d_in[5];
    const float* gamma = (const float*)d_in[6];
    const float* beta  = (const float*)d_in[7];
    const float* w2    = (const float*)d_in[8];
    const float* b2    = (const float*)d_in[9];
    const float* clsw  = (const float*)d_in[10];
    const float* clsb  = (const float*)d_in[11];
    float* out = (float*)d_out;

    cudaFuncSetAttribute(k5_attn, cudaFuncAttributeMaxDynamicSharedMemorySize, K5_SMEM);

    k1_protos<<<dim3(72, B), 256>>>(sup, st);
    k1b_norms<<<BI, 512>>>();
    k2_qnorms<<<BJ, 288>>>(query);
    k3_conv1<<<BJ, 256>>>(query, w1, b1);
    k4_bn<<<2*MID, 256>>>(gamma, beta);
    k5_attn<<<BJ, 256, K5_SMEM>>>(query, qt, w2, b2, out + LOGITS_N);
    k6_logits<<<BJ, 144>>>(query, clsw, clsb, out);
}